// round 9
// baseline (speedup 1.0000x reference)
#include <cuda_runtime.h>
#include <cstdint>
#include <math.h>

#define SEQLEN   2048
#define HIDDEN   4096
#define NUM_HEADS 32
#define NUM_KV_HEADS 2
#define HEAD_DIM 128
#define QKV_OUT  ((NUM_HEADS + 2 * NUM_KV_HEADS) * HEAD_DIM)   // 4608
#define NQ       (NUM_HEADS * HEAD_DIM)                        // 4096
#define NKV      (NUM_KV_HEADS * HEAD_DIM)                     // 256
#define REP      (NUM_HEADS / NUM_KV_HEADS)                    // 16

// Scratch (device globals; no allocation allowed in kernel_launch)
__device__ float g_qkv[SEQLEN * QKV_OUT];        // ~37.7 MB
__device__ float g_attn[SEQLEN * NQ];            // ~33.5 MB
__device__ float g_Ar[SEQLEN * HIDDEN];          // 32 MB  (tf32-rounded A)
__device__ float g_Br[HIDDEN * QKV_OUT];         // 72 MB  (tf32-rounded B)
__device__ float g_vt[NUM_KV_HEADS * HEAD_DIM * SEQLEN];  // 2 MB, V dim-major

// ===========================================================================
// helpers
// ===========================================================================
__device__ __forceinline__ float tf32_round(float f) {
    uint32_t u;
    asm("cvt.rna.tf32.f32 %0, %1;" : "=r"(u) : "f"(f));
    return __uint_as_float(u);
}
__device__ __forceinline__ uint32_t smem_u32(const void* p) {
    uint32_t a;
    asm("{ .reg .u64 t; cvta.to.shared.u64 t, %1; cvt.u32.u64 %0, t; }"
        : "=r"(a) : "l"(p));
    return a;
}
__device__ __forceinline__ void cp_async16(uint32_t dst, const void* src) {
    asm volatile("cp.async.cg.shared.global [%0], [%1], 16;" :: "r"(dst), "l"(src));
}
#define CP_COMMIT() asm volatile("cp.async.commit_group;" ::: "memory")
#define CP_WAIT1()  asm volatile("cp.async.wait_group 1;" ::: "memory")

__device__ __forceinline__ void mma_tf32(float* c, const uint32_t* a, const uint32_t* b) {
    asm volatile(
        "mma.sync.aligned.m16n8k8.row.col.f32.tf32.tf32.f32 "
        "{%0,%1,%2,%3}, {%4,%5,%6,%7}, {%8,%9}, {%0,%1,%2,%3};"
        : "+f"(c[0]), "+f"(c[1]), "+f"(c[2]), "+f"(c[3])
        : "r"(a[0]), "r"(a[1]), "r"(a[2]), "r"(a[3]), "r"(b[0]), "r"(b[1]));
}
__device__ __forceinline__ void ldsm_x4(uint32_t& r0, uint32_t& r1,
                                        uint32_t& r2, uint32_t& r3, uint32_t addr) {
    asm volatile("ldmatrix.sync.aligned.m8n8.x4.shared.b16 {%0,%1,%2,%3}, [%4];"
        : "=r"(r0), "=r"(r1), "=r"(r2), "=r"(r3) : "r"(addr));
}

// ===========================================================================
// elementwise tf32 rounding pass (float4 vectorized; in-place allowed)
// ===========================================================================
__global__ void round_tf32_kernel(const float* __restrict__ in,
                                  float* __restrict__ out, int n4)
{
    int i = blockIdx.x * blockDim.x + threadIdx.x;
    if (i >= n4) return;
    float4 v = ((const float4*)in)[i];
    v.x = tf32_round(v.x); v.y = tf32_round(v.y);
    v.z = tf32_round(v.z); v.w = tf32_round(v.w);
    ((float4*)out)[i] = v;
}

// ===========================================================================
// Fused RoPE + tf32 rounding of qkv (in place) + dim-major V copy to g_vt.
// ===========================================================================
__global__ void rope_round_kernel(const float* __restrict__ cosb,
                                  const float* __restrict__ sinb)
{
    const int HALF = QKV_OUT / 2;
    int idx = blockIdx.x * blockDim.x + threadIdx.x;
    if (idx >= SEQLEN * HALF) return;
    int s = idx / HALF;
    int c = (idx - s * HALF) * 2;
    float2* p = (float2*)(g_qkv + (size_t)s * QKV_OUT + c);
    float2 v = *p;
    int head = c >> 7, dim = c & 127;
    if (head < NUM_HEADS + NUM_KV_HEADS && dim < 64) {
        int pair = dim >> 1;
        float cs = cosb[s * 64 + pair];
        float sn = sinb[s * 64 + pair];
        float x0 = v.x, x1 = v.y;
        v.x = x0 * cs - x1 * sn;
        v.y = x1 * cs + x0 * sn;
    }
    v.x = tf32_round(v.x);
    v.y = tf32_round(v.y);
    *p = v;
    if (head >= NUM_HEADS + NUM_KV_HEADS) {   // V heads -> dim-major copy
        int kvh = head - (NUM_HEADS + NUM_KV_HEADS);
        g_vt[((size_t)(kvh * HEAD_DIM + dim))     * SEQLEN + s] = v.x;
        g_vt[((size_t)(kvh * HEAD_DIM + dim + 1)) * SEQLEN + s] = v.y;
    }
}

// ===========================================================================
// tf32 mma.sync GEMM: C[M,N] = A[M,K] @ B[K,N] (+bias)   (at HMMA roofline)
// ===========================================================================
#define ASTR 36
#define BSTR 136
#define A_FL (128 * ASTR)
#define B_FL (32 * BSTR)
#define STAGE_FL (A_FL + B_FL)
#define GSMEM_BYTES (3 * STAGE_FL * 4)

template <bool HAS_BIAS>
__global__ __launch_bounds__(256)
void gemm_mma(const float* __restrict__ A, const float* __restrict__ B,
              const float* __restrict__ bias, float* __restrict__ C,
              int K, int ldb, int N)
{
    extern __shared__ float smem[];
    const uint32_t sbase = smem_u32(smem);

    const int tid  = threadIdx.x;
    const int warp = tid >> 5;
    const int lane = tid & 31;
    const int g    = lane >> 2;
    const int t    = lane & 3;
    const int wm   = warp & 1;
    const int wn   = warp >> 1;
    const int brow = blockIdx.y * 128;
    const int n0   = blockIdx.x * 128;

    const int ga_row = lane & 15;
    const int ga_col = (lane >> 4) << 2;

    auto load_stage = [&](int s, int k0) {
        const float* Ap = A + (size_t)brow * K + k0;
        const float* Bp = B + (size_t)k0 * ldb + n0;
        const uint32_t sA = sbase + (uint32_t)s * (STAGE_FL * 4);
        const uint32_t sB = sA + A_FL * 4;
        #pragma unroll
        for (int p = 0; p < 4; p++) {
            int id = tid + p * 256;
            int r = id >> 3, c = (id & 7) << 2;
            cp_async16(sA + (uint32_t)(r * ASTR + c) * 4, Ap + (size_t)r * K + c);
        }
        #pragma unroll
        for (int p = 0; p < 4; p++) {
            int id = tid + p * 256;
            int r = id >> 5, c = (id & 31) << 2;
            cp_async16(sB + (uint32_t)(r * BSTR + c) * 4, Bp + (size_t)r * ldb + c);
        }
    };

    const int iters = K / 32;
    load_stage(0, 0);  CP_COMMIT();
    load_stage(1, 32); CP_COMMIT();

    float acc[4][4][4];
    #pragma unroll
    for (int mt = 0; mt < 4; mt++)
        #pragma unroll
        for (int nt = 0; nt < 4; nt++)
            #pragma unroll
            for (int q = 0; q < 4; q++) acc[mt][nt][q] = 0.0f;

    for (int i = 0; i < iters; i++) {
        CP_WAIT1();
        __syncthreads();
        if (i + 2 < iters) load_stage((i + 2) % 3, (i + 2) * 32);
        CP_COMMIT();

        const uint32_t sA = sbase + (uint32_t)(i % 3) * (STAGE_FL * 4);
        const float* Bs = smem + (i % 3) * STAGE_FL + A_FL;

        #pragma unroll
        for (int kk = 0; kk < 4; kk++) {
            const int k = kk * 8;
            uint32_t a[4][4];
            #pragma unroll
            for (int mt = 0; mt < 4; mt++) {
                uint32_t addr = sA + (uint32_t)((wm * 64 + mt * 16 + ga_row) * ASTR + k + ga_col) * 4;
                ldsm_x4(a[mt][0], a[mt][1], a[mt][2], a[mt][3], addr);
            }
            uint32_t b[4][2];
            #pragma unroll
            for (int nt = 0; nt < 4; nt++) {
                const float* bp = Bs + (k + t) * BSTR + wn * 32 + nt * 8 + g;
                b[nt][0] = __float_as_uint(bp[0]);
                b[nt][1] = __float_as_uint(bp[4 * BSTR]);
            }
            #pragma unroll
            for (int mt = 0; mt < 4; mt++)
                #pragma unroll
                for (int nt = 0; nt < 4; nt++)
                    mma_tf32(acc[mt][nt], a[mt], b[nt]);
        }
    }

    #pragma unroll
    for (int mt = 0; mt < 4; mt++) {
        #pragma unroll
        for (int nt = 0; nt < 4; nt++) {
            const int row = brow + wm * 64 + mt * 16 + g;
            const int col = n0 + wn * 32 + nt * 8 + 2 * t;
            float bx = 0.f, by = 0.f;
            if (HAS_BIAS) { bx = bias[col]; by = bias[col + 1]; }
            float2 v0 = make_float2(acc[mt][nt][0] + bx, acc[mt][nt][1] + by);
            float2 v1 = make_float2(acc[mt][nt][2] + bx, acc[mt][nt][3] + by);
            *(float2*)&C[(size_t)row * N + col]       = v0;
            *(float2*)&C[(size_t)(row + 8) * N + col] = v1;
        }
    }
}

// ===========================================================================
// Flash attention (causal, GQA rep=16), tf32 mma.sync + ldmatrix.
// BM=64 (4 warps / 128 threads), BN=32, 3-stage cp.async, 2 CTAs per SM:
// two independent CTAs interleave so one CTA's softmax overlaps the other's
// mma work on the tensor pipe.
// ===========================================================================
#define FBM 64
#define FBN 32
#define KSTR 132
#define VSTR2 36
#define K_FL (FBN * KSTR)            // 4224
#define V_FL (HEAD_DIM * VSTR2)      // 4608
#define FSTAGE_FL (K_FL + V_FL)      // 8832
#define FSMEM_BYTES (3 * FSTAGE_FL * 4)   // 105984

__global__ __launch_bounds__(128, 2) void flash_tc(float* __restrict__ out)
{
    extern __shared__ float fs[];
    const uint32_t sbase = smem_u32(fs);

    const int tid  = threadIdx.x;
    const int warp = tid >> 5;
    const int lane = tid & 31;
    const int g    = lane >> 2;
    const int t    = lane & 3;
    const int h    = blockIdx.y;
    const int kvh  = h / REP;
    const int qi   = gridDim.x - 1 - blockIdx.x;   // big blocks first
    const int q0   = qi * FBM;
    const int r0   = q0 + warp * 16 + g;
    const int r1   = r0 + 8;
    const float scale = 0.08838834764831845f;

    // ldmatrix lane mappings
    const int kq_row = (lane & 7) + ((lane >> 4) << 3);   // key offset 0..15
    const int kq_dim = ((lane >> 3) & 1) << 2;            // 0 or 4
    const int pv_dim = (lane & 7) + ((lane >> 4) << 3);   // dim offset 0..15
    const int pv_key = ((lane >> 3) & 1) << 2;            // 0 or 4

    // ---- Q fragments, pre-scaled + tf32-rounded, resident in registers ----
    uint32_t qa[16][4];
    {
        const float* qb = g_qkv + (size_t)(q0 + warp * 16) * QKV_OUT + h * HEAD_DIM;
        #pragma unroll
        for (int ks = 0; ks < 16; ks++) {
            qa[ks][0] = __float_as_uint(tf32_round(qb[(size_t)g       * QKV_OUT + ks * 8 + t]     * scale));
            qa[ks][1] = __float_as_uint(tf32_round(qb[(size_t)(g + 8) * QKV_OUT + ks * 8 + t]     * scale));
            qa[ks][2] = __float_as_uint(tf32_round(qb[(size_t)g       * QKV_OUT + ks * 8 + t + 4] * scale));
            qa[ks][3] = __float_as_uint(tf32_round(qb[(size_t)(g + 8) * QKV_OUT + ks * 8 + t + 4] * scale));
        }
    }

    auto load_kv = [&](int s, int kb) {
        const uint32_t sK = sbase + (uint32_t)s * (FSTAGE_FL * 4);
        const uint32_t sV = sK + K_FL * 4;
        const float* ksrc = g_qkv + (size_t)(kb * FBN) * QKV_OUT + NQ + kvh * HEAD_DIM;
        const float* vsrc = g_vt + (size_t)(kvh * HEAD_DIM) * SEQLEN + kb * FBN;
        #pragma unroll
        for (int p = 0; p < 8; p++) {
            int id = tid + p * 128;
            int r = id >> 5;             // key 0..31
            int c = (id & 31) << 2;      // dim 0..124
            cp_async16(sK + (uint32_t)(r * KSTR + c) * 4, ksrc + (size_t)r * QKV_OUT + c);
        }
        #pragma unroll
        for (int p = 0; p < 8; p++) {
            int id = tid + p * 128;
            int r = id >> 3;             // dim 0..127
            int c = (id & 7) << 2;       // key 0..28
            cp_async16(sV + (uint32_t)(r * VSTR2 + c) * 4, vsrc + (size_t)r * SEQLEN + c);
        }
    };

    float o[16][4];
    #pragma unroll
    for (int d = 0; d < 16; d++)
        #pragma unroll
        for (int q = 0; q < 4; q++) o[d][q] = 0.0f;
    float m0 = -1e30f, m1 = -1e30f, l0 = 0.0f, l1 = 0.0f;

    const int nkb = (q0 + FBM) / FBN;
    load_kv(0, 0); CP_COMMIT();
    load_kv(1, 1); CP_COMMIT();

    const int srcA = (lane & ~3) | (t >> 1);
    const int srcB = srcA + 2;
    const int selo = t & 1;

    for (int kb = 0; kb < nkb; kb++) {
        CP_WAIT1();
        __syncthreads();
        if (kb + 2 < nkb) load_kv((kb + 2) % 3, kb + 2);
        CP_COMMIT();

        const uint32_t sKu = sbase + (uint32_t)(kb % 3) * (FSTAGE_FL * 4);
        const uint32_t sVu = sKu + K_FL * 4;

        // ---- S = Q K^T (scaled); B-frags via ldmatrix.x4 (2 j-tiles/op) ----
        float sc[4][4];
        #pragma unroll
        for (int j = 0; j < 4; j++)
            #pragma unroll
            for (int q = 0; q < 4; q++) sc[j][q] = 0.0f;

        #pragma unroll
        for (int ks = 0; ks < 16; ks++) {
            #pragma unroll
            for (int jp = 0; jp < 2; jp++) {
                uint32_t b0, b1, b2, b3;
                uint32_t addr = sKu + (uint32_t)((jp * 16 + kq_row) * KSTR + ks * 8 + kq_dim) * 4;
                ldsm_x4(b0, b1, b2, b3, addr);
                uint32_t bb0[2] = { b0, b1 };
                uint32_t bb1[2] = { b2, b3 };
                mma_tf32(sc[2 * jp],     qa[ks], bb0);
                mma_tf32(sc[2 * jp + 1], qa[ks], bb1);
            }
        }

        // ---- causal mask (only the last two 32-key blocks can cross) ----
        if (kb >= nkb - 2) {
            const int keyb = kb * FBN + 2 * t;
            #pragma unroll
            for (int j = 0; j < 4; j++) {
                int k0 = keyb + j * 8;
                if (k0     > r0) sc[j][0] = -1e30f;
                if (k0 + 1 > r0) sc[j][1] = -1e30f;
                if (k0     > r1) sc[j][2] = -1e30f;
                if (k0 + 1 > r1) sc[j][3] = -1e30f;
            }
        }

        // ---- online softmax ----
        float mx0 = -1e30f, mx1 = -1e30f;
        #pragma unroll
        for (int j = 0; j < 4; j++) {
            mx0 = fmaxf(mx0, fmaxf(sc[j][0], sc[j][1]));
            mx1 = fmaxf(mx1, fmaxf(sc[j][2], sc[j][3]));
        }
        mx0 = fmaxf(mx0, __shfl_xor_sync(0xffffffffu, mx0, 1));
        mx0 = fmaxf(mx0, __shfl_xor_sync(0xffffffffu, mx0, 2));
        mx1 = fmaxf(mx1, __shfl_xor_sync(0xffffffffu, mx1, 1));
        mx1 = fmaxf(mx1, __shfl_xor_sync(0xffffffffu, mx1, 2));
        const float mn0 = fmaxf(m0, mx0);
        const float mn1 = fmaxf(m1, mx1);
        const float c0 = __expf(m0 - mn0);
        const float c1 = __expf(m1 - mn1);
        m0 = mn0; m1 = mn1;
        l0 *= c0;  l1 *= c1;
        #pragma unroll
        for (int d = 0; d < 16; d++) {
            o[d][0] *= c0; o[d][1] *= c0;
            o[d][2] *= c1; o[d][3] *= c1;
        }

        uint32_t pc[4][4];
        #pragma unroll
        for (int j = 0; j < 4; j++) {
            float p0 = __expf(sc[j][0] - m0);
            float p1 = __expf(sc[j][1] - m0);
            float p2 = __expf(sc[j][2] - m1);
            float p3 = __expf(sc[j][3] - m1);
            l0 += p0 + p1;
            l1 += p2 + p3;
            pc[j][0] = __float_as_uint(tf32_round(p0));
            pc[j][1] = __float_as_uint(tf32_round(p1));
            pc[j][2] = __float_as_uint(tf32_round(p2));
            pc[j][3] = __float_as_uint(tf32_round(p3));
        }

        // ---- O += P V; A-frag via quad shuffles, B-frag via ldmatrix.x4 ----
        #pragma unroll
        for (int j = 0; j < 4; j++) {
            uint32_t a[4];
            uint32_t x0 = __shfl_sync(0xffffffffu, pc[j][0], srcA);
            uint32_t x1 = __shfl_sync(0xffffffffu, pc[j][1], srcA);
            uint32_t x2 = __shfl_sync(0xffffffffu, pc[j][2], srcA);
            uint32_t x3 = __shfl_sync(0xffffffffu, pc[j][3], srcA);
            a[0] = selo ? x1 : x0;
            a[1] = selo ? x3 : x2;
            uint32_t y0 = __shfl_sync(0xffffffffu, pc[j][0], srcB);
            uint32_t y1 = __shfl_sync(0xffffffffu, pc[j][1], srcB);
            uint32_t y2 = __shfl_sync(0xffffffffu, pc[j][2], srcB);
            uint32_t y3 = __shfl_sync(0xffffffffu, pc[j][3], srcB);
            a[2] = selo ? y1 : y0;
            a[3] = selo ? y3 : y2;

            #pragma unroll
            for (int dp = 0; dp < 8; dp++) {
                uint32_t v0, v1, v2, v3;
                uint32_t addr = sVu + (uint32_t)((dp * 16 + pv_dim) * VSTR2 + j * 8 + pv_key) * 4;
                ldsm_x4(v0, v1, v2, v3, addr);
                uint32_t bb0[2] = { v0, v1 };
                uint32_t bb1[2] = { v2, v3 };
                mma_tf32(o[2 * dp],     a, bb0);
                mma_tf32(o[2 * dp + 1], a, bb1);
            }
        }
    }

    // ---- finalize ----
    l0 += __shfl_xor_sync(0xffffffffu, l0, 1);
    l0 += __shfl_xor_sync(0xffffffffu, l0, 2);
    l1 += __shfl_xor_sync(0xffffffffu, l1, 1);
    l1 += __shfl_xor_sync(0xffffffffu, l1, 2);
    const float inv0 = 1.0f / l0;
    const float inv1 = 1.0f / l1;

    float* op0 = out + (size_t)r0 * NQ + h * HEAD_DIM + 2 * t;
    float* op1 = out + (size_t)r1 * NQ + h * HEAD_DIM + 2 * t;
    #pragma unroll
    for (int d = 0; d < 16; d++) {
        float2 v0 = make_float2(tf32_round(o[d][0] * inv0), tf32_round(o[d][1] * inv0));
        float2 v1 = make_float2(tf32_round(o[d][2] * inv1), tf32_round(o[d][3] * inv1));
        *(float2*)(op0 + d * 8) = v0;
        *(float2*)(op1 + d * 8) = v1;
    }
}

// ---------------------------------------------------------------------------
// Launch
// ---------------------------------------------------------------------------
extern "C" void kernel_launch(void* const* d_in, const int* in_sizes, int n_in,
                              void* d_out, int out_size)
{
    const float* hidden = (const float*)d_in[0];
    const float* cosb   = (const float*)d_in[1];
    const float* sinb   = (const float*)d_in[2];
    const float* w_qkv  = (const float*)d_in[3];
    const float* b_qkv  = (const float*)d_in[4];
    const float* w_o    = (const float*)d_in[5];
    float* out = (float*)d_out;

    float *qkv = nullptr, *attn = nullptr, *Ar = nullptr, *Br = nullptr;
    cudaGetSymbolAddress((void**)&qkv,  g_qkv);
    cudaGetSymbolAddress((void**)&attn, g_attn);
    cudaGetSymbolAddress((void**)&Ar,   g_Ar);
    cudaGetSymbolAddress((void**)&Br,   g_Br);

    cudaFuncSetAttribute(gemm_mma<true>,  cudaFuncAttributeMaxDynamicSharedMemorySize, GSMEM_BYTES);
    cudaFuncSetAttribute(gemm_mma<false>, cudaFuncAttributeMaxDynamicSharedMemorySize, GSMEM_BYTES);
    cudaFuncSetAttribute(flash_tc,        cudaFuncAttributeMaxDynamicSharedMemorySize, FSMEM_BYTES);

    // 0) tf32-round GEMM1 operands
    {
        int n4 = SEQLEN * HIDDEN / 4;
        round_tf32_kernel<<<(n4 + 255) / 256, 256>>>(hidden, Ar, n4);
        n4 = HIDDEN * QKV_OUT / 4;
        round_tf32_kernel<<<(n4 + 255) / 256, 256>>>(w_qkv, Br, n4);
    }

    // 1) QKV projection + bias (tf32 mma.sync)
    gemm_mma<true><<<dim3(QKV_OUT / 128, SEQLEN / 128), 256, GSMEM_BYTES>>>(
        Ar, Br, b_qkv, qkv, HIDDEN, QKV_OUT, QKV_OUT);

    // 2) fused RoPE + tf32-round + dim-major V copy
    {
        int total = SEQLEN * (QKV_OUT / 2);
        rope_round_kernel<<<(total + 255) / 256, 256>>>(cosb, sinb);
    }

    // 3) causal GQA flash attention on tensor cores (2 CTAs/SM)
    flash_tc<<<dim3(SEQLEN / FBM, NUM_HEADS), 128, FSMEM_BYTES>>>(attn);

    // 4) tf32-round w_o (stream-ordered after GEMM1: safe to reuse Br)
    {
        int n4 = NQ * HIDDEN / 4;
        round_tf32_kernel<<<(n4 + 255) / 256, 256>>>(w_o, Br, n4);
    }

    // 5) output projection (tf32 mma.sync)
    gemm_mma<false><<<dim3(HIDDEN / 128, SEQLEN / 128), 256, GSMEM_BYTES>>>(
        attn, Br, nullptr, out, NQ, HIDDEN, HIDDEN);
}